// round 16
// baseline (speedup 1.0000x reference)
#include <cuda_runtime.h>
#include <math.h>

// Cross-block reduction scratch (zero at module load; last block re-zeroes
// after each launch so every graph replay starts from a clean state).
__device__ double g_sum;
__device__ unsigned int g_done;

__device__ __forceinline__ float row_loss(float4 p, float4 t)
{
    const float DELTA = 0.1f;
    const float inv3  = 1.0f / 3.0f;

    float mp = (p.x + p.y + p.z + p.w) * 0.25f;
    float mt = (t.x + t.y + t.z + t.w) * 0.25f;

    float dpx = p.x - mp, dpy = p.y - mp, dpz = p.z - mp, dpw = p.w - mp;
    float dtx = t.x - mt, dty = t.y - mt, dtz = t.z - mt, dtw = t.w - mt;

    float var_p = (dpx*dpx + dpy*dpy + dpz*dpz + dpw*dpw) * inv3;
    float var_t = (dtx*dtx + dty*dty + dtz*dtz + dtw*dtw) * inv3;
    float cov   = (dpx*dtx + dpy*dty + dpz*dtz + dpw*dtw) * inv3;

    float a1 = 2.0f * mp * mt + DELTA;
    float a2 = 2.0f * cov + DELTA;
    float b1 = mp * mp + mt * mt + DELTA;
    float b2 = var_p + var_t + DELTA;

    // rcp.approx+mul: ~2 ulp on O(1) operands, far inside the 1e-3 tolerance.
    return 1.0f - __fdividef(a1 * a2, b1 * b2 + DELTA);
}

__global__ void __launch_bounds__(256, 8)
ssim_loss_kernel(const float4* __restrict__ pred,
                 const float4* __restrict__ target,
                 float* __restrict__ out,
                 int n_rows)
{
    float local = 0.0f;
    const int stride = gridDim.x * blockDim.x;
    const int tid0   = blockIdx.x * blockDim.x + threadIdx.x;

    // Counted main loop: every thread runs exactly n_rows/stride full
    // iterations (no per-iter bounds branch), then one predicated tail.
    const int full_iters = n_rows / stride;

    int i = tid0;
    #pragma unroll 1
    for (int n = 0; n < full_iters; n++, i += stride) {
        float4 p = __ldcg(&pred[i]);
        float4 t = __ldcg(&target[i]);
        local += row_loss(p, t);
    }
    if (i < n_rows) {
        local += row_loss(__ldcg(&pred[i]), __ldcg(&target[i]));
    }

    // Warp reduction
    #pragma unroll
    for (int off = 16; off > 0; off >>= 1)
        local += __shfl_down_sync(0xFFFFFFFFu, local, off);

    __shared__ float warp_sums[8];
    int lane = threadIdx.x & 31;
    int wid  = threadIdx.x >> 5;
    if (lane == 0) warp_sums[wid] = local;
    __syncthreads();

    if (wid == 0) {
        float bs = (lane < 8) ? warp_sums[lane] : 0.0f;
        #pragma unroll
        for (int off = 4; off > 0; off >>= 1)
            bs += __shfl_down_sync(0xFFFFFFFFu, bs, off);

        if (lane == 0) {
            atomicAdd(&g_sum, (double)bs);
            __threadfence();
            unsigned int prev = atomicAdd(&g_done, 1u);
            if (prev == gridDim.x - 1) {
                // Last block: finalize and reset state for the next replay.
                double mean = g_sum / (double)n_rows;
                float r = (float)mean;
                if (isnan(r)) r = 1.0f;   // reference NaN fallback == 1.0
                out[0] = r;
                g_sum = 0.0;
                g_done = 0u;
                __threadfence();
            }
        }
    }
}

extern "C" void kernel_launch(void* const* d_in, const int* in_sizes, int n_in,
                              void* d_out, int out_size)
{
    const float4* pred   = (const float4*)d_in[0];
    const float4* target = (const float4*)d_in[1];
    float* out = (float*)d_out;

    int n_rows = in_sizes[0] / 4;   // [N, 4] float32 -> N rows of float4

    const int threads = 256;
    int blocks = 152 * 8;           // GB300: 152 SMs, one full wave = 1216
    int max_blocks = (n_rows + threads - 1) / threads;
    if (blocks > max_blocks) blocks = max_blocks;

    ssim_loss_kernel<<<blocks, threads>>>(pred, target, out, n_rows);
}